// round 1
// baseline (speedup 1.0000x reference)
#include <cuda_runtime.h>
#include <cuda_bf16.h>
#include <cstdint>

// Problem dims (fixed by the dataset)
#define BB 32
#define SS 1024
#define II 256
#define HH 512
#define OO 256
#define MROWS (BB * SS)   // 32768

// Scratch (allocation-free rule: __device__ globals)
__device__ float g_ic[(size_t)MROWS * HH];   // 64 MB input currents
__device__ float g_spk[(size_t)MROWS * HH];  // 64 MB spikes (fp32 0/1)

// ---------------------------------------------------------------------------
// Simple register-blocked SGEMM: C[M,N] = A[M,K] @ B[K,N], all row-major fp32.
// BM=128, BN=64, BK=16, TM=8, TN=4, 256 threads. Dims must divide tiles.
// ---------------------------------------------------------------------------
template <int BM, int BN, int BK, int TM, int TN>
__global__ __launch_bounds__(256) void sgemm_kernel(
    const float* __restrict__ A, const float* __restrict__ Bm,
    float* __restrict__ C, int M, int N, int K)
{
    __shared__ float As[BK][BM];
    __shared__ float Bs[BK][BN];

    const int tid = threadIdx.x;
    const int mBlock = blockIdx.y * BM;
    const int nBlock = blockIdx.x * BN;

    const int tCols = BN / TN;          // 16
    const int tRow = tid / tCols;       // 0..15
    const int tCol = tid % tCols;       // 0..15

    float acc[TM][TN];
#pragma unroll
    for (int i = 0; i < TM; i++)
#pragma unroll
        for (int j = 0; j < TN; j++) acc[i][j] = 0.f;

    for (int k0 = 0; k0 < K; k0 += BK) {
        // Load A tile (BM x BK) as float4 along K, store transposed
#pragma unroll
        for (int it = 0; it < (BM * BK) / (256 * 4); it++) {
            int f = tid + it * 256;             // float4 index
            int m = f / (BK / 4);
            int kq = f % (BK / 4);
            float4 v = *reinterpret_cast<const float4*>(
                &A[(size_t)(mBlock + m) * K + k0 + kq * 4]);
            As[kq * 4 + 0][m] = v.x;
            As[kq * 4 + 1][m] = v.y;
            As[kq * 4 + 2][m] = v.z;
            As[kq * 4 + 3][m] = v.w;
        }
        // Load B tile (BK x BN)
#pragma unroll
        for (int it = 0; it < (BK * BN) / (256 * 4); it++) {
            int f = tid + it * 256;
            int k = f / (BN / 4);
            int nq = f % (BN / 4);
            float4 v = *reinterpret_cast<const float4*>(
                &Bm[(size_t)(k0 + k) * N + nBlock + nq * 4]);
            *reinterpret_cast<float4*>(&Bs[k][nq * 4]) = v;
        }
        __syncthreads();

#pragma unroll
        for (int k = 0; k < BK; k++) {
            float ra[TM], rb[TN];
#pragma unroll
            for (int i = 0; i < TM; i++) ra[i] = As[k][tRow * TM + i];
#pragma unroll
            for (int j = 0; j < TN; j++) rb[j] = Bs[k][tCol * TN + j];
#pragma unroll
            for (int i = 0; i < TM; i++)
#pragma unroll
                for (int j = 0; j < TN; j++) acc[i][j] += ra[i] * rb[j];
        }
        __syncthreads();
    }

#pragma unroll
    for (int i = 0; i < TM; i++) {
        float* crow = &C[(size_t)(mBlock + tRow * TM + i) * N + nBlock + tCol * TN];
#pragma unroll
        for (int j = 0; j < TN; j += 4) {
            float4 v = make_float4(acc[i][j], acc[i][j + 1], acc[i][j + 2], acc[i][j + 3]);
            *reinterpret_cast<float4*>(&crow[j]) = v;
        }
    }
}

// ---------------------------------------------------------------------------
// Recurrent scan. One CTA per batch (32 CTAs), 512 threads (one per neuron h).
// State (mp, refrac) in registers. Lateral = sparse gather over firing set:
//   lateral[h] = sum_{j in firing} W_lat[j, h]
// Firing list rebuilt every step via warp ballots. Gather is float4-wide:
// thread handles 4 h-columns, list split into 4 shards (g = tid>>7), partial
// sums reduced through shared memory.
// ---------------------------------------------------------------------------
__global__ __launch_bounds__(512, 1) void snn_scan_kernel(
    const float* __restrict__ ic, const float* __restrict__ Wlat,
    const float* __restrict__ thr, float* __restrict__ spk)
{
    __shared__ float4 part4[4][HH / 4];   // 8 KB partial lateral sums
    __shared__ unsigned masks_s[16];
    __shared__ int list_s[HH];

    const int b = blockIdx.x;
    const int tid = threadIdx.x;
    const int lane = tid & 31;
    const int warp = tid >> 5;
    const int g = tid >> 7;       // shard 0..3
    const int hq = tid & 127;     // float4 column group

    float* partf = reinterpret_cast<float*>(part4);
    const float4* Wl4 = reinterpret_cast<const float4*>(Wlat);  // row j: Wl4[j*128 + hq]

    float mp = 0.f;
    int refrac = 0;
    int ns = 0;
    const float thrv = thr[tid];

    const size_t rowbase = (size_t)b * SS * HH;
    float ic_cur = ic[rowbase + tid];

    for (int t = 0; t < SS; ++t) {
        float ic_nxt = (t < SS - 1) ? ic[rowbase + (size_t)(t + 1) * HH + tid] : 0.f;

        // --- lateral partials over this thread's shard of the firing list ---
        float ax = 0.f, ay = 0.f, az = 0.f, aw = 0.f;
        float bx = 0.f, by = 0.f, bz = 0.f, bw = 0.f;
        int k = g;
        for (; k + 4 < ns; k += 8) {
            int j0 = list_s[k];
            int j1 = list_s[k + 4];
            float4 w0 = Wl4[(size_t)j0 * (HH / 4) + hq];
            float4 w1 = Wl4[(size_t)j1 * (HH / 4) + hq];
            ax += w0.x; ay += w0.y; az += w0.z; aw += w0.w;
            bx += w1.x; by += w1.y; bz += w1.z; bw += w1.w;
        }
        for (; k < ns; k += 4) {
            int j0 = list_s[k];
            float4 w0 = Wl4[(size_t)j0 * (HH / 4) + hq];
            ax += w0.x; ay += w0.y; az += w0.z; aw += w0.w;
        }
        ax += bx; ay += by; az += bz; aw += bw;
        part4[g][hq] = make_float4(ax, ay, az, aw);
        __syncthreads();

        // --- membrane update (exact reference semantics, fp32) ---
        float lat = partf[0 * HH + tid] + partf[1 * HH + tid] +
                    partf[2 * HH + tid] + partf[3 * HH + tid];
        mp = 0.95f * mp + ic_cur - lat;
        if (refrac > 0) mp = 0.f;
        refrac = (refrac > 0) ? (refrac - 1) : 0;
        bool spike = (mp >= thrv);
        spk[rowbase + (size_t)t * HH + tid] = spike ? 1.f : 0.f;
        if (spike) { mp = 0.f; refrac = 2; }

        // --- rebuild firing list ---
        unsigned m = __ballot_sync(0xffffffffu, spike);
        if (lane == 0) masks_s[warp] = m;
        __syncthreads();

        int tot = 0, base = 0;
#pragma unroll
        for (int w = 0; w < 16; ++w) {
            if (w == warp) base = tot;
            tot += __popc(masks_s[w]);
        }
        if (spike) {
            int pos = base + __popc(m & ((1u << lane) - 1u));
            list_s[pos] = tid;
        }
        ns = tot;
        ic_cur = ic_nxt;
        __syncthreads();   // list_s visible before next step's gather
    }
}

// ---------------------------------------------------------------------------
// Launch
// ---------------------------------------------------------------------------
extern "C" void kernel_launch(void* const* d_in, const int* in_sizes, int n_in,
                              void* d_out, int out_size)
{
    const float* x    = (const float*)d_in[0];  // [B,S,I]
    const float* Win  = (const float*)d_in[1];  // [I,H]
    const float* Wlat = (const float*)d_in[2];  // [H,H]
    const float* Wout = (const float*)d_in[3];  // [H,O]
    const float* thr  = (const float*)d_in[4];  // [H]
    float* out = (float*)d_out;                 // [B,S,O]

    float *ic, *spk;
    cudaGetSymbolAddress((void**)&ic, g_ic);
    cudaGetSymbolAddress((void**)&spk, g_spk);

    // GEMM1: ic = x @ Win   (32768 x 512 x 256)
    {
        dim3 grid(HH / 64, MROWS / 128);
        sgemm_kernel<128, 64, 16, 8, 4><<<grid, 256>>>(x, Win, ic, MROWS, HH, II);
    }

    // Recurrent scan: 32 CTAs x 512 threads
    snn_scan_kernel<<<BB, 512>>>(ic, Wlat, thr, spk);

    // GEMM3: out = spk @ Wout   (32768 x 256 x 512)
    {
        dim3 grid(OO / 64, MROWS / 128);
        sgemm_kernel<128, 64, 16, 8, 4><<<grid, 256>>>(spk, Wout, out, MROWS, OO, HH);
    }
}